// round 5
// baseline (speedup 1.0000x reference)
#include <cuda_runtime.h>
#include <mma.h>
#include <math.h>

using namespace nvcuda;

// Problem shape (fixed by setup_inputs)
#define Bsz 4096
#define Dd  1024
#define Rr  256
#define STEPS 8

static __device__ float g_P[(size_t)Bsz * Rr];   // Christoffel intermediate P = tanh(xU)*(vU)^2

// Tiling
constexpr int BM = 64, BN = 64, BK = 32;
constexpr int LDA = BK + 8;   // 40  (multiple of 8, skewed)
constexpr int LDB = BN + 8;   // 72
constexpr int LDG = BN + 8;   // 72

__device__ __forceinline__ float to_tf32(float x) { return wmma::__float_to_tf32(x); }

// ---------------------------------------------------------------------------
// Kernel A: gate = X@U, h = V@U (shared U tile), P = tanh(gate)*h*h  -> g_P
// X,V: [B,D] row-major fp32; U: [D,R] row-major fp32. Grid: (R/BN, B/BM), 128 thr.
// ---------------------------------------------------------------------------
__global__ void __launch_bounds__(128)
kA(const float* __restrict__ X, const float* __restrict__ V,
   const float* __restrict__ U)
{
    __shared__ float sX[BM * LDA];
    __shared__ float sV[BM * LDA];
    __shared__ float sU[BK * LDB];

    const int bn = blockIdx.x, bm = blockIdx.y;
    const int tid  = threadIdx.x;
    const int warp = tid >> 5;
    const int wRow = (warp & 1) * 32;
    const int wCol = (warp >> 1) * 32;

    wmma::fragment<wmma::accumulator, 16, 16, 8, float> accX[2][2], accV[2][2];
    #pragma unroll
    for (int i = 0; i < 2; i++)
        #pragma unroll
        for (int j = 0; j < 2; j++) {
            wmma::fill_fragment(accX[i][j], 0.0f);
            wmma::fill_fragment(accV[i][j], 0.0f);
        }

    const float* Xg = X + (size_t)bm * BM * Dd;
    const float* Vg = V + (size_t)bm * BM * Dd;

    for (int k0 = 0; k0 < Dd; k0 += BK) {
        // X / V tiles: 64 rows x 32 cols = 512 float4
        #pragma unroll
        for (int it = 0; it < 4; it++) {
            int t  = tid + it * 128;
            int r  = t >> 3, c4 = t & 7;
            float4 x4 = *(const float4*)(Xg + (size_t)r * Dd + k0 + c4 * 4);
            float4 v4 = *(const float4*)(Vg + (size_t)r * Dd + k0 + c4 * 4);
            float* dx = &sX[r * LDA + c4 * 4];
            dx[0] = to_tf32(x4.x); dx[1] = to_tf32(x4.y);
            dx[2] = to_tf32(x4.z); dx[3] = to_tf32(x4.w);
            float* dv = &sV[r * LDA + c4 * 4];
            dv[0] = to_tf32(v4.x); dv[1] = to_tf32(v4.y);
            dv[2] = to_tf32(v4.z); dv[3] = to_tf32(v4.w);
        }
        // U tile: 32 rows x 64 cols = 512 float4
        #pragma unroll
        for (int it = 0; it < 4; it++) {
            int t  = tid + it * 128;
            int r  = t >> 4, c4 = t & 15;
            float4 u4 = *(const float4*)(U + (size_t)(k0 + r) * Rr + bn * BN + c4 * 4);
            float* du = &sU[r * LDB + c4 * 4];
            du[0] = to_tf32(u4.x); du[1] = to_tf32(u4.y);
            du[2] = to_tf32(u4.z); du[3] = to_tf32(u4.w);
        }
        __syncthreads();

        #pragma unroll
        for (int kk = 0; kk < BK; kk += 8) {
            wmma::fragment<wmma::matrix_a, 16, 16, 8, wmma::precision::tf32, wmma::row_major> ax[2], av[2];
            wmma::fragment<wmma::matrix_b, 16, 16, 8, wmma::precision::tf32, wmma::row_major> bu[2];
            #pragma unroll
            for (int i = 0; i < 2; i++) {
                wmma::load_matrix_sync(ax[i], &sX[(wRow + i * 16) * LDA + kk], LDA);
                wmma::load_matrix_sync(av[i], &sV[(wRow + i * 16) * LDA + kk], LDA);
            }
            #pragma unroll
            for (int j = 0; j < 2; j++)
                wmma::load_matrix_sync(bu[j], &sU[kk * LDB + wCol + j * 16], LDB);
            #pragma unroll
            for (int i = 0; i < 2; i++)
                #pragma unroll
                for (int j = 0; j < 2; j++) {
                    wmma::mma_sync(accX[i][j], ax[i], bu[j], accX[i][j]);
                    wmma::mma_sync(accV[i][j], av[i], bu[j], accV[i][j]);
                }
        }
        __syncthreads();
    }

    // Fused epilogue: P = tanh(gate) * h * h  (fragment layouts match elementwise)
    float* Pg = g_P + (size_t)bm * BM * Rr + bn * BN;
    #pragma unroll
    for (int i = 0; i < 2; i++)
        #pragma unroll
        for (int j = 0; j < 2; j++) {
            #pragma unroll
            for (int e = 0; e < accX[i][j].num_elements; e++) {
                float h = accV[i][j].x[e];
                accX[i][j].x[e] = to_tf32(tanhf(accX[i][j].x[e]) * h * h);
            }
            wmma::store_matrix_sync(Pg + (size_t)(wRow + i * 16) * Rr + wCol + j * 16,
                                    accX[i][j], Rr, wmma::mem_row_major);
        }
}

// ---------------------------------------------------------------------------
// Kernel B: gamma = P@W, fused Verlet epilogue.
//  FIRST:  a = F - gamma; v = v + hdt*a;  x = x + dt*v      (v becomes v_half)
//  !FIRST: a = F - gamma; v = v + hdt*a
// P: [B,R] (g_P), W: [R,D] row-major. Grid: (D/BN, B/BM), 128 thr.
// ---------------------------------------------------------------------------
template <bool FIRST>
__global__ void __launch_bounds__(128)
kB(const float* __restrict__ W, const float* __restrict__ F,
   float* __restrict__ Xw, float* __restrict__ Vw)
{
    __shared__ float smem[BM * LDA + BK * LDB];   // 4864 floats; gamma stage needs 64*72=4608
    float* sP = smem;
    float* sW = smem + BM * LDA;

    const int bn = blockIdx.x, bm = blockIdx.y;
    const int tid  = threadIdx.x;
    const int warp = tid >> 5;
    const int wRow = (warp & 1) * 32;
    const int wCol = (warp >> 1) * 32;

    wmma::fragment<wmma::accumulator, 16, 16, 8, float> acc[2][2];
    #pragma unroll
    for (int i = 0; i < 2; i++)
        #pragma unroll
        for (int j = 0; j < 2; j++) wmma::fill_fragment(acc[i][j], 0.0f);

    const float* Pg = g_P + (size_t)bm * BM * Rr;

    for (int k0 = 0; k0 < Rr; k0 += BK) {
        // P tile: 64 x 32 (already tf32-rounded when written)
        #pragma unroll
        for (int it = 0; it < 4; it++) {
            int t = tid + it * 128;
            int r = t >> 3, c4 = t & 7;
            *(float4*)&sP[r * LDA + c4 * 4] =
                *(const float4*)(Pg + (size_t)r * Rr + k0 + c4 * 4);
        }
        // W tile: 32 x 64
        #pragma unroll
        for (int it = 0; it < 4; it++) {
            int t = tid + it * 128;
            int r = t >> 4, c4 = t & 15;
            float4 w4 = *(const float4*)(W + (size_t)(k0 + r) * Dd + bn * BN + c4 * 4);
            float* dw = &sW[r * LDB + c4 * 4];
            dw[0] = to_tf32(w4.x); dw[1] = to_tf32(w4.y);
            dw[2] = to_tf32(w4.z); dw[3] = to_tf32(w4.w);
        }
        __syncthreads();

        #pragma unroll
        for (int kk = 0; kk < BK; kk += 8) {
            wmma::fragment<wmma::matrix_a, 16, 16, 8, wmma::precision::tf32, wmma::row_major> af[2];
            wmma::fragment<wmma::matrix_b, 16, 16, 8, wmma::precision::tf32, wmma::row_major> bf[2];
            #pragma unroll
            for (int i = 0; i < 2; i++)
                wmma::load_matrix_sync(af[i], &sP[(wRow + i * 16) * LDA + kk], LDA);
            #pragma unroll
            for (int j = 0; j < 2; j++)
                wmma::load_matrix_sync(bf[j], &sW[kk * LDB + wCol + j * 16], LDB);
            #pragma unroll
            for (int i = 0; i < 2; i++)
                #pragma unroll
                for (int j = 0; j < 2; j++)
                    wmma::mma_sync(acc[i][j], af[i], bf[j], acc[i][j]);
        }
        __syncthreads();
    }

    // Stage gamma tile in smem (reuse), then fused elementwise Verlet update
    float* sG = smem;
    #pragma unroll
    for (int i = 0; i < 2; i++)
        #pragma unroll
        for (int j = 0; j < 2; j++)
            wmma::store_matrix_sync(&sG[(wRow + i * 16) * LDG + wCol + j * 16],
                                    acc[i][j], LDG, wmma::mem_row_major);
    __syncthreads();

    const float dt = 0.01f, hdt = 0.005f;
    const int base_row = bm * BM, base_col = bn * BN;
    #pragma unroll
    for (int it = 0; it < 8; it++) {            // 1024 float4s / 128 threads
        int u  = tid + it * 128;
        int r  = u >> 4, c4 = u & 15;
        float4 g = *(float4*)&sG[r * LDG + c4 * 4];
        size_t idx = (size_t)(base_row + r) * Dd + base_col + c4 * 4;
        float4 f = *(const float4*)(F + idx);
        float4 v = *(float4*)(Vw + idx);
        v.x += hdt * (f.x - g.x);
        v.y += hdt * (f.y - g.y);
        v.z += hdt * (f.z - g.z);
        v.w += hdt * (f.w - g.w);
        if (FIRST) {
            float4 x = *(float4*)(Xw + idx);
            x.x += dt * v.x; x.y += dt * v.y; x.z += dt * v.z; x.w += dt * v.w;
            *(float4*)(Xw + idx) = x;
        }
        *(float4*)(Vw + idx) = v;
    }
}

// ---------------------------------------------------------------------------
extern "C" void kernel_launch(void* const* d_in, const int* in_sizes, int n_in,
                              void* d_out, int out_size)
{
    const float* x0 = (const float*)d_in[0];
    const float* v0 = (const float*)d_in[1];
    const float* F  = (const float*)d_in[2];
    const float* U  = (const float*)d_in[3];
    const float* W  = (const float*)d_in[4];
    // d_in[5] = steps (device int); fixed at 8 by the problem definition.

    float* Xw = (float*)d_out;                    // output x, used as working buffer
    float* Vw = Xw + (size_t)Bsz * Dd;            // output v, used as working buffer

    cudaMemcpyAsync(Xw, x0, sizeof(float) * (size_t)Bsz * Dd, cudaMemcpyDeviceToDevice, 0);
    cudaMemcpyAsync(Vw, v0, sizeof(float) * (size_t)Bsz * Dd, cudaMemcpyDeviceToDevice, 0);

    dim3 blk(128);
    dim3 gA(Rr / BN, Bsz / BM);   // (4, 64)
    dim3 gB(Dd / BN, Bsz / BM);   // (16, 64)

    for (int s = 0; s < STEPS; s++) {
        kA<<<gA, blk>>>(Xw, Vw, U);          // P from (x, v)
        kB<true><<<gB, blk>>>(W, F, Xw, Vw); // v -> v_half, x -> x + dt*v_half
        kA<<<gA, blk>>>(Xw, Vw, U);          // P from (x_new, v_half)
        kB<false><<<gB, blk>>>(W, F, Xw, Vw);// v_half -> v
    }
}

// round 7
// speedup vs baseline: 1.0996x; 1.0996x over previous
#include <cuda_runtime.h>
#include <mma.h>
#include <math.h>

using namespace nvcuda;

#define Bsz 4096
#define Dd  1024
#define Rr  256
#define STEPS 8

static __device__ float g_P[(size_t)Bsz * Rr];

// ---------------- cp.async helpers ----------------
__device__ __forceinline__ void cp_async16(void* sptr, const void* gptr) {
    unsigned s = (unsigned)__cvta_generic_to_shared(sptr);
    asm volatile("cp.async.cg.shared.global [%0], [%1], 16;\n" :: "r"(s), "l"(gptr));
}
__device__ __forceinline__ void cp_commit() { asm volatile("cp.async.commit_group;\n"); }
template <int N> __device__ __forceinline__ void cp_wait() {
    asm volatile("cp.async.wait_group %0;\n" :: "n"(N));
}

// ===========================================================================
// Kernel A: gate = X@U, h = V@U (shared U tile), P = tanh(gate)*h*h -> g_P
// Tile 128x64, BK=32, 256 thr, 2-stage cp.async pipeline.
// Grid (Rr/64=4, Bsz/128=32) = 128 blocks.
// ===========================================================================
constexpr int A_LDA   = 40;                         // 32+8
constexpr int A_LDU   = 72;                         // 64+8
constexpr int A_STAGE = 128 * A_LDA * 2 + 32 * A_LDU;   // sX + sV + sU = 12544
constexpr int A_SMEM_BYTES = 2 * A_STAGE * 4;           // 100352

__global__ void __launch_bounds__(256, 2)
kA(const float* __restrict__ X, const float* __restrict__ V,
   const float* __restrict__ U)
{
    extern __shared__ float smem[];
    const int bn = blockIdx.x, bm = blockIdx.y;
    const int tid  = threadIdx.x;
    const int warp = tid >> 5;
    const int wRow = (warp & 3) * 32;    // 4 warps in M
    const int wCol = (warp >> 2) * 32;   // 2 warps in N

    wmma::fragment<wmma::accumulator, 16, 16, 8, float> accX[2][2], accV[2][2];
    #pragma unroll
    for (int i = 0; i < 2; i++)
        #pragma unroll
        for (int j = 0; j < 2; j++) {
            wmma::fill_fragment(accX[i][j], 0.0f);
            wmma::fill_fragment(accV[i][j], 0.0f);
        }

    const float* Xg = X + (size_t)bm * 128 * Dd;
    const float* Vg = V + (size_t)bm * 128 * Dd;
    const float* Ug = U + bn * 64;

    auto load_tile = [&](int kt, int stg) {
        float* sX = smem + stg * A_STAGE;
        float* sV = sX + 128 * A_LDA;
        float* sU = sV + 128 * A_LDA;
        const int k0 = kt * 32;
        #pragma unroll
        for (int it = 0; it < 4; it++) {           // 128x32 = 1024 f4
            int t = tid + it * 256;
            int r = t >> 3, c4 = t & 7;
            cp_async16(&sX[r * A_LDA + c4 * 4], Xg + (size_t)r * Dd + k0 + c4 * 4);
        }
        #pragma unroll
        for (int it = 0; it < 4; it++) {
            int t = tid + it * 256;
            int r = t >> 3, c4 = t & 7;
            cp_async16(&sV[r * A_LDA + c4 * 4], Vg + (size_t)r * Dd + k0 + c4 * 4);
        }
        #pragma unroll
        for (int it = 0; it < 2; it++) {           // 32x64 = 512 f4
            int t = tid + it * 256;
            int r = t >> 4, c4 = t & 15;
            cp_async16(&sU[r * A_LDU + c4 * 4], Ug + (size_t)(k0 + r) * Rr + c4 * 4);
        }
        cp_commit();
    };

    constexpr int KT = Dd / 32;   // 32
    load_tile(0, 0);
    for (int kt = 0; kt < KT; kt++) {
        if (kt + 1 < KT) { load_tile(kt + 1, (kt + 1) & 1); cp_wait<1>(); }
        else             { cp_wait<0>(); }
        __syncthreads();

        const float* sX = smem + (kt & 1) * A_STAGE;
        const float* sV = sX + 128 * A_LDA;
        const float* sU = sV + 128 * A_LDA;

        #pragma unroll
        for (int kk = 0; kk < 32; kk += 8) {
            wmma::fragment<wmma::matrix_a, 16, 16, 8, wmma::precision::tf32, wmma::row_major> ax[2], av[2];
            wmma::fragment<wmma::matrix_b, 16, 16, 8, wmma::precision::tf32, wmma::row_major> bu[2];
            #pragma unroll
            for (int i = 0; i < 2; i++) {
                wmma::load_matrix_sync(ax[i], &sX[(wRow + i * 16) * A_LDA + kk], A_LDA);
                wmma::load_matrix_sync(av[i], &sV[(wRow + i * 16) * A_LDA + kk], A_LDA);
            }
            #pragma unroll
            for (int j = 0; j < 2; j++)
                wmma::load_matrix_sync(bu[j], &sU[kk * A_LDU + wCol + j * 16], A_LDU);
            #pragma unroll
            for (int i = 0; i < 2; i++)
                #pragma unroll
                for (int j = 0; j < 2; j++) {
                    wmma::mma_sync(accX[i][j], ax[i], bu[j], accX[i][j]);
                    wmma::mma_sync(accV[i][j], av[i], bu[j], accV[i][j]);
                }
        }
        __syncthreads();
    }

    // Fused epilogue: P = tanh(gate) * h * h
    float* Pg = g_P + (size_t)bm * 128 * Rr + bn * 64;
    #pragma unroll
    for (int i = 0; i < 2; i++)
        #pragma unroll
        for (int j = 0; j < 2; j++) {
            #pragma unroll
            for (int e = 0; e < accX[i][j].num_elements; e++) {
                float h = accV[i][j].x[e];
                accX[i][j].x[e] = tanhf(accX[i][j].x[e]) * h * h;
            }
            wmma::store_matrix_sync(Pg + (size_t)(wRow + i * 16) * Rr + wCol + j * 16,
                                    accX[i][j], Rr, wmma::mem_row_major);
        }
}

// ===========================================================================
// Kernel B: gamma = P@W, fused Verlet epilogue.
// Tile 128x128, BK=32, 256 thr, 2-stage cp.async pipeline.
// Grid (Dd/128=8, Bsz/128=32) = 256 blocks -> 2 CTAs/SM, single wave.
// ===========================================================================
constexpr int B_LDP   = 40;                         // 32+8
constexpr int B_LDW   = 136;                        // 128+8
constexpr int B_STAGE = 128 * B_LDP + 32 * B_LDW;   // 5120+4352 = 9472
constexpr int B_LDG_  = 132;
constexpr int B_SMEM_FLOATS = (2 * B_STAGE > 128 * B_LDG_) ? 2 * B_STAGE : 128 * B_LDG_;
constexpr int B_SMEM_BYTES  = B_SMEM_FLOATS * 4;    // 75776

template <bool FIRST>
__global__ void __launch_bounds__(256, 2)
kB(const float* __restrict__ W, const float* __restrict__ F,
   float* __restrict__ Xw, float* __restrict__ Vw)
{
    extern __shared__ float smem[];
    const int bn = blockIdx.x, bm = blockIdx.y;
    const int tid  = threadIdx.x;
    const int warp = tid >> 5;
    const int wRow = (warp & 3) * 32;    // 4 warps in M
    const int wCol = (warp >> 2) * 64;   // 2 warps in N (64 cols each)

    wmma::fragment<wmma::accumulator, 16, 16, 8, float> acc[2][4];
    #pragma unroll
    for (int i = 0; i < 2; i++)
        #pragma unroll
        for (int j = 0; j < 4; j++) wmma::fill_fragment(acc[i][j], 0.0f);

    const float* Pg = g_P + (size_t)bm * 128 * Rr;
    const float* Wg = W + bn * 128;

    auto load_tile = [&](int kt, int stg) {
        float* sP = smem + stg * B_STAGE;
        float* sW = sP + 128 * B_LDP;
        const int k0 = kt * 32;
        #pragma unroll
        for (int it = 0; it < 4; it++) {           // 128x32
            int t = tid + it * 256;
            int r = t >> 3, c4 = t & 7;
            cp_async16(&sP[r * B_LDP + c4 * 4], Pg + (size_t)r * Rr + k0 + c4 * 4);
        }
        #pragma unroll
        for (int it = 0; it < 4; it++) {           // 32x128
            int t = tid + it * 256;
            int r = t >> 5, c4 = t & 31;
            cp_async16(&sW[r * B_LDW + c4 * 4], Wg + (size_t)(k0 + r) * Dd + c4 * 4);
        }
        cp_commit();
    };

    constexpr int KT = Rr / 32;   // 8
    load_tile(0, 0);
    for (int kt = 0; kt < KT; kt++) {
        if (kt + 1 < KT) { load_tile(kt + 1, (kt + 1) & 1); cp_wait<1>(); }
        else             { cp_wait<0>(); }
        __syncthreads();

        const float* sP = smem + (kt & 1) * B_STAGE;
        const float* sW = sP + 128 * B_LDP;

        #pragma unroll
        for (int kk = 0; kk < 32; kk += 8) {
            wmma::fragment<wmma::matrix_a, 16, 16, 8, wmma::precision::tf32, wmma::row_major> af[2];
            wmma::fragment<wmma::matrix_b, 16, 16, 8, wmma::precision::tf32, wmma::row_major> bf[4];
            #pragma unroll
            for (int i = 0; i < 2; i++)
                wmma::load_matrix_sync(af[i], &sP[(wRow + i * 16) * B_LDP + kk], B_LDP);
            #pragma unroll
            for (int j = 0; j < 4; j++)
                wmma::load_matrix_sync(bf[j], &sW[kk * B_LDW + wCol + j * 16], B_LDW);
            #pragma unroll
            for (int i = 0; i < 2; i++)
                #pragma unroll
                for (int j = 0; j < 4; j++)
                    wmma::mma_sync(acc[i][j], af[i], bf[j], acc[i][j]);
        }
        __syncthreads();
    }

    // Stage gamma tile in smem, then fused Verlet update
    float* sG = smem;
    #pragma unroll
    for (int i = 0; i < 2; i++)
        #pragma unroll
        for (int j = 0; j < 4; j++)
            wmma::store_matrix_sync(&sG[(wRow + i * 16) * B_LDG_ + wCol + j * 16],
                                    acc[i][j], B_LDG_, wmma::mem_row_major);
    __syncthreads();

    const float dt = 0.01f, hdt = 0.005f;
    const int base_row = bm * 128, base_col = bn * 128;
    #pragma unroll
    for (int it = 0; it < 16; it++) {              // 128*128/4 = 4096 f4 / 256 thr
        int u  = tid + it * 256;
        int r  = u >> 5, c4 = u & 31;
        float4 g = *(float4*)&sG[r * B_LDG_ + c4 * 4];
        size_t idx = (size_t)(base_row + r) * Dd + base_col + c4 * 4;
        float4 f = *(const float4*)(F + idx);
        float4 v = *(float4*)(Vw + idx);
        v.x += hdt * (f.x - g.x);
        v.y += hdt * (f.y - g.y);
        v.z += hdt * (f.z - g.z);
        v.w += hdt * (f.w - g.w);
        if (FIRST) {
            float4 x = *(float4*)(Xw + idx);
            x.x += dt * v.x; x.y += dt * v.y; x.z += dt * v.z; x.w += dt * v.w;
            *(float4*)(Xw + idx) = x;
        }
        *(float4*)(Vw + idx) = v;
    }
}

// ===========================================================================
extern "C" void kernel_launch(void* const* d_in, const int* in_sizes, int n_in,
                              void* d_out, int out_size)
{
    const float* x0 = (const float*)d_in[0];
    const float* v0 = (const float*)d_in[1];
    const float* F  = (const float*)d_in[2];
    const float* U  = (const float*)d_in[3];
    const float* W  = (const float*)d_in[4];

    float* Xw = (float*)d_out;
    float* Vw = Xw + (size_t)Bsz * Dd;

    cudaFuncSetAttribute(kA, cudaFuncAttributeMaxDynamicSharedMemorySize, A_SMEM_BYTES);
    cudaFuncSetAttribute(kB<true>,  cudaFuncAttributeMaxDynamicSharedMemorySize, B_SMEM_BYTES);
    cudaFuncSetAttribute(kB<false>, cudaFuncAttributeMaxDynamicSharedMemorySize, B_SMEM_BYTES);

    cudaMemcpyAsync(Xw, x0, sizeof(float) * (size_t)Bsz * Dd, cudaMemcpyDeviceToDevice, 0);
    cudaMemcpyAsync(Vw, v0, sizeof(float) * (size_t)Bsz * Dd, cudaMemcpyDeviceToDevice, 0);

    dim3 blk(256);
    dim3 gA(Rr / 64, Bsz / 128);    // (4, 32)  = 128 blocks
    dim3 gB(Dd / 128, Bsz / 128);   // (8, 32)  = 256 blocks

    for (int s = 0; s < STEPS; s++) {
        kA<<<gA, blk, A_SMEM_BYTES>>>(Xw, Vw, U);
        kB<true><<<gB, blk, B_SMEM_BYTES>>>(W, F, Xw, Vw);
        kA<<<gA, blk, A_SMEM_BYTES>>>(Xw, Vw, U);
        kB<false><<<gB, blk, B_SMEM_BYTES>>>(W, F, Xw, Vw);
    }
}

// round 9
// speedup vs baseline: 4.1343x; 3.7599x over previous
#include <cuda_runtime.h>
#include <mma.h>
#include <math.h>

using namespace nvcuda;

#define Bsz 4096
#define Dd  1024
#define Rr  256

// ---------------- device scratch ----------------
static __device__ float g_hx[(size_t)Bsz * Rr];
static __device__ float g_hv[(size_t)Bsz * Rr];
static __device__ float g_fU[(size_t)Bsz * Rr];
static __device__ float g_P [(size_t)Bsz * Rr];
static __device__ float g_Sv[(size_t)Bsz * Rr];
static __device__ float g_Sx[(size_t)Bsz * Rr];
static __device__ float g_WU [(size_t)Rr * Rr];
static __device__ float g_WUp[(size_t)8 * Rr * Rr];

// ---------------- cp.async helpers ----------------
__device__ __forceinline__ void cp_async16(void* sptr, const void* gptr) {
    unsigned s = (unsigned)__cvta_generic_to_shared(sptr);
    asm volatile("cp.async.cg.shared.global [%0], [%1], 16;\n" :: "r"(s), "l"(gptr));
}
__device__ __forceinline__ void cp_commit() { asm volatile("cp.async.commit_group;\n"); }
template <int N> __device__ __forceinline__ void cp_wait() {
    asm volatile("cp.async.wait_group %0;\n" :: "n"(N));
}

typedef wmma::fragment<wmma::accumulator, 16, 16, 8, float> AccF;
typedef wmma::fragment<wmma::matrix_a, 16, 16, 8, wmma::precision::tf32, wmma::row_major> AF;
typedef wmma::fragment<wmma::matrix_b, 16, 16, 8, wmma::precision::tf32, wmma::row_major> BF;

// ===========================================================================
// kInit: hx = X@U, hv = V@U, fU = F@U (triple GEMM sharing U tile).
// Epilogue: P0 = tanh(hx)*hv^2 ; Sv = P0 ; Sx = 8*P0.
// Tile 128x64, K=1024, BK=32, 2-stage cp.async. Grid (4, 32), 256 thr.
// ===========================================================================
constexpr int I_LDA = 40, I_LDU = 72;
constexpr int I_STAGE = 3 * 128 * I_LDA + 32 * I_LDU;   // 17664 floats
constexpr int I_SMEM  = 2 * I_STAGE * 4;                // 141312 B

__global__ void __launch_bounds__(256, 1)
kInit(const float* __restrict__ X, const float* __restrict__ V,
      const float* __restrict__ Fin, const float* __restrict__ U)
{
    extern __shared__ float smem[];
    const int bn = blockIdx.x, bm = blockIdx.y;
    const int tid = threadIdx.x, warp = tid >> 5;
    const int wRow = (warp & 3) * 32, wCol = (warp >> 2) * 32;

    AccF acc[3][2][2];
    #pragma unroll
    for (int o = 0; o < 3; o++)
        #pragma unroll
        for (int i = 0; i < 2; i++)
            #pragma unroll
            for (int j = 0; j < 2; j++) wmma::fill_fragment(acc[o][i][j], 0.0f);

    const float* Ag[3] = { X + (size_t)bm * 128 * Dd,
                           V + (size_t)bm * 128 * Dd,
                           Fin + (size_t)bm * 128 * Dd };
    const float* Ug = U + bn * 64;

    auto load_stage = [&](int kt, int s) {
        float* st = smem + s * I_STAGE;
        const int k0 = kt * 32;
        #pragma unroll
        for (int o = 0; o < 3; o++) {
            float* sA = st + o * 128 * I_LDA;
            #pragma unroll
            for (int it = 0; it < 4; it++) {
                int t = tid + it * 256;
                int r = t >> 3, c4 = t & 7;
                cp_async16(&sA[r * I_LDA + c4 * 4], Ag[o] + (size_t)r * Dd + k0 + c4 * 4);
            }
        }
        float* sU = st + 3 * 128 * I_LDA;
        #pragma unroll
        for (int it = 0; it < 2; it++) {
            int t = tid + it * 256;
            int r = t >> 4, c4 = t & 15;
            cp_async16(&sU[r * I_LDU + c4 * 4], Ug + (size_t)(k0 + r) * Rr + c4 * 4);
        }
        cp_commit();
    };

    constexpr int KT = Dd / 32;
    load_stage(0, 0);
    for (int kt = 0; kt < KT; kt++) {
        if (kt + 1 < KT) { load_stage(kt + 1, (kt + 1) & 1); cp_wait<1>(); }
        else             { cp_wait<0>(); }
        __syncthreads();
        const float* st = smem + (kt & 1) * I_STAGE;
        const float* sU = st + 3 * 128 * I_LDA;
        #pragma unroll
        for (int kk = 0; kk < 32; kk += 8) {
            AF af[3][2]; BF bu[2];
            #pragma unroll
            for (int o = 0; o < 3; o++)
                #pragma unroll
                for (int i = 0; i < 2; i++)
                    wmma::load_matrix_sync(af[o][i],
                        st + o * 128 * I_LDA + (wRow + i * 16) * I_LDA + kk, I_LDA);
            #pragma unroll
            for (int j = 0; j < 2; j++)
                wmma::load_matrix_sync(bu[j], sU + kk * I_LDU + wCol + j * 16, I_LDU);
            #pragma unroll
            for (int o = 0; o < 3; o++)
                #pragma unroll
                for (int i = 0; i < 2; i++)
                    #pragma unroll
                    for (int j = 0; j < 2; j++)
                        wmma::mma_sync(acc[o][i][j], af[o][i], bu[j], acc[o][i][j]);
        }
        __syncthreads();
    }

    // Epilogue
    #pragma unroll
    for (int i = 0; i < 2; i++)
        #pragma unroll
        for (int j = 0; j < 2; j++) {
            size_t off = (size_t)(bm * 128 + wRow + i * 16) * Rr + bn * 64 + wCol + j * 16;
            wmma::store_matrix_sync(g_hx + off, acc[0][i][j], Rr, wmma::mem_row_major);
            wmma::store_matrix_sync(g_hv + off, acc[1][i][j], Rr, wmma::mem_row_major);
            wmma::store_matrix_sync(g_fU + off, acc[2][i][j], Rr, wmma::mem_row_major);
            #pragma unroll
            for (int e = 0; e < acc[0][i][j].num_elements; e++) {
                float h = acc[1][i][j].x[e];
                acc[0][i][j].x[e] = tanhf(acc[0][i][j].x[e]) * h * h;
            }
            wmma::store_matrix_sync(g_P  + off, acc[0][i][j], Rr, wmma::mem_row_major);
            wmma::store_matrix_sync(g_Sv + off, acc[0][i][j], Rr, wmma::mem_row_major);
            #pragma unroll
            for (int e = 0; e < acc[0][i][j].num_elements; e++)
                acc[0][i][j].x[e] *= 8.0f;
            wmma::store_matrix_sync(g_Sx + off, acc[0][i][j], Rr, wmma::mem_row_major);
        }
}

// ===========================================================================
// kWU: WU = W@U  [256,1024]@[1024,256], split-K (8 x 128). Grid (2,2,8).
// ===========================================================================
constexpr int W_LDA = 40, W_LDB = 136;
constexpr int W_STAGE = 128 * W_LDA + 32 * W_LDB;   // 9472 floats
constexpr int W_SMEM  = 2 * W_STAGE * 4;            // 75776 B

__global__ void __launch_bounds__(256, 1)
kWU(const float* __restrict__ W, const float* __restrict__ U)
{
    extern __shared__ float smem[];
    const int bnn = blockIdx.x, bm = blockIdx.y, kz = blockIdx.z;
    const int tid = threadIdx.x, warp = tid >> 5;
    const int wRow = (warp & 3) * 32, wCol = (warp >> 2) * 64;

    AccF acc[2][4];
    #pragma unroll
    for (int i = 0; i < 2; i++)
        #pragma unroll
        for (int j = 0; j < 4; j++) wmma::fill_fragment(acc[i][j], 0.0f);

    const float* Ag = W + (size_t)bm * 128 * Dd + kz * 128;
    const float* Bg = U + (size_t)kz * 128 * Rr + bnn * 128;

    auto load_stage = [&](int kt, int s) {
        float* sA = smem + s * W_STAGE;
        float* sB = sA + 128 * W_LDA;
        const int k0 = kt * 32;
        #pragma unroll
        for (int it = 0; it < 4; it++) {
            int t = tid + it * 256;
            int r = t >> 3, c4 = t & 7;
            cp_async16(&sA[r * W_LDA + c4 * 4], Ag + (size_t)r * Dd + k0 + c4 * 4);
        }
        #pragma unroll
        for (int it = 0; it < 4; it++) {
            int t = tid + it * 256;
            int r = t >> 5, c4 = t & 31;
            cp_async16(&sB[r * W_LDB + c4 * 4], Bg + (size_t)(k0 + r) * Rr + c4 * 4);
        }
        cp_commit();
    };

    constexpr int KT = 4;
    load_stage(0, 0);
    for (int kt = 0; kt < KT; kt++) {
        if (kt + 1 < KT) { load_stage(kt + 1, (kt + 1) & 1); cp_wait<1>(); }
        else             { cp_wait<0>(); }
        __syncthreads();
        const float* sA = smem + (kt & 1) * W_STAGE;
        const float* sB = sA + 128 * W_LDA;
        #pragma unroll
        for (int kk = 0; kk < 32; kk += 8) {
            AF af[2]; BF bf[4];
            #pragma unroll
            for (int i = 0; i < 2; i++)
                wmma::load_matrix_sync(af[i], sA + (wRow + i * 16) * W_LDA + kk, W_LDA);
            #pragma unroll
            for (int j = 0; j < 4; j++)
                wmma::load_matrix_sync(bf[j], sB + kk * W_LDB + wCol + j * 16, W_LDB);
            #pragma unroll
            for (int i = 0; i < 2; i++)
                #pragma unroll
                for (int j = 0; j < 4; j++)
                    wmma::mma_sync(acc[i][j], af[i], bf[j], acc[i][j]);
        }
        __syncthreads();
    }

    float* out = g_WUp + (size_t)kz * Rr * Rr;
    #pragma unroll
    for (int i = 0; i < 2; i++)
        #pragma unroll
        for (int j = 0; j < 4; j++)
            wmma::store_matrix_sync(out + (size_t)(bm * 128 + wRow + i * 16) * Rr
                                        + bnn * 128 + wCol + j * 16,
                                    acc[i][j], Rr, wmma::mem_row_major);
}

__global__ void kRed() {
    int i = blockIdx.x * 256 + threadIdx.x;
    float s = 0.0f;
    #pragma unroll
    for (int z = 0; z < 8; z++) s += g_WUp[(size_t)z * Rr * Rr + i];
    g_WU[i] = s;
}

// ===========================================================================
// kStep<UPDX>: gamma = P@WU  [4096,256]@[256,256]; fused reduced-space update.
//   hv += hdt*(fU - gamma); if UPDX: hx += dt*hv;
//   Pn = tanh(hx)*hv^2; P = Pn; Sv += Pn; Sx += wq*Pn.
// Tile 128x64, K=256, BK=32, grid (4,32), 256 thr.
// ===========================================================================
constexpr int S_LDA = 40, S_LDB = 72, S_LDG = 68;
constexpr int S_STAGE = 128 * S_LDA + 32 * S_LDB;   // 7424
constexpr int S_SMEM_F = (2 * S_STAGE > 128 * S_LDG) ? 2 * S_STAGE : 128 * S_LDG;
constexpr int S_SMEM   = S_SMEM_F * 4;              // 59392 B

template <bool UPDX>
__global__ void __launch_bounds__(256, 1)
kStep(float wq)
{
    extern __shared__ float smem[];
    const int bn = blockIdx.x, bm = blockIdx.y;
    const int tid = threadIdx.x, warp = tid >> 5;
    const int wRow = (warp & 3) * 32, wCol = (warp >> 2) * 32;

    AccF acc[2][2];
    #pragma unroll
    for (int i = 0; i < 2; i++)
        #pragma unroll
        for (int j = 0; j < 2; j++) wmma::fill_fragment(acc[i][j], 0.0f);

    const float* Pg = g_P + (size_t)bm * 128 * Rr;
    const float* Bg = g_WU + bn * 64;

    auto load_stage = [&](int kt, int s) {
        float* sA = smem + s * S_STAGE;
        float* sB = sA + 128 * S_LDA;
        const int k0 = kt * 32;
        #pragma unroll
        for (int it = 0; it < 4; it++) {
            int t = tid + it * 256;
            int r = t >> 3, c4 = t & 7;
            cp_async16(&sA[r * S_LDA + c4 * 4], Pg + (size_t)r * Rr + k0 + c4 * 4);
        }
        #pragma unroll
        for (int it = 0; it < 2; it++) {
            int t = tid + it * 256;
            int r = t >> 4, c4 = t & 15;
            cp_async16(&sB[r * S_LDB + c4 * 4], Bg + (size_t)(k0 + r) * Rr + c4 * 4);
        }
        cp_commit();
    };

    constexpr int KT = Rr / 32;   // 8
    load_stage(0, 0);
    for (int kt = 0; kt < KT; kt++) {
        if (kt + 1 < KT) { load_stage(kt + 1, (kt + 1) & 1); cp_wait<1>(); }
        else             { cp_wait<0>(); }
        __syncthreads();
        const float* sA = smem + (kt & 1) * S_STAGE;
        const float* sB = sA + 128 * S_LDA;
        #pragma unroll
        for (int kk = 0; kk < 32; kk += 8) {
            AF af[2]; BF bf[2];
            #pragma unroll
            for (int i = 0; i < 2; i++)
                wmma::load_matrix_sync(af[i], sA + (wRow + i * 16) * S_LDA + kk, S_LDA);
            #pragma unroll
            for (int j = 0; j < 2; j++)
                wmma::load_matrix_sync(bf[j], sB + kk * S_LDB + wCol + j * 16, S_LDB);
            #pragma unroll
            for (int i = 0; i < 2; i++)
                #pragma unroll
                for (int j = 0; j < 2; j++)
                    wmma::mma_sync(acc[i][j], af[i], bf[j], acc[i][j]);
        }
        __syncthreads();
    }

    // stage gamma, then fused elementwise update
    float* sG = smem;
    #pragma unroll
    for (int i = 0; i < 2; i++)
        #pragma unroll
        for (int j = 0; j < 2; j++)
            wmma::store_matrix_sync(&sG[(wRow + i * 16) * S_LDG + wCol + j * 16],
                                    acc[i][j], S_LDG, wmma::mem_row_major);
    __syncthreads();

    const float dt = 0.01f, hdt = 0.005f;
    #pragma unroll
    for (int it = 0; it < 8; it++) {            // 128 rows x 16 f4 = 2048 f4
        int u = tid + it * 256;
        int r = u >> 4, c4 = u & 15;
        float4 g = *(float4*)&sG[r * S_LDG + c4 * 4];
        size_t idx = (size_t)(bm * 128 + r) * Rr + bn * 64 + c4 * 4;
        float4 hv = *(float4*)(g_hv + idx);
        float4 fu = *(const float4*)(g_fU + idx);
        hv.x += hdt * (fu.x - g.x);
        hv.y += hdt * (fu.y - g.y);
        hv.z += hdt * (fu.z - g.z);
        hv.w += hdt * (fu.w - g.w);
        *(float4*)(g_hv + idx) = hv;
        float4 hx = *(float4*)(g_hx + idx);
        if (UPDX) {
            hx.x += dt * hv.x; hx.y += dt * hv.y;
            hx.z += dt * hv.z; hx.w += dt * hv.w;
            *(float4*)(g_hx + idx) = hx;
        }
        float4 p;
        p.x = tanhf(hx.x) * hv.x * hv.x;
        p.y = tanhf(hx.y) * hv.y * hv.y;
        p.z = tanhf(hx.z) * hv.z * hv.z;
        p.w = tanhf(hx.w) * hv.w * hv.w;
        *(float4*)(g_P + idx) = p;
        float4 sv = *(float4*)(g_Sv + idx);
        sv.x += p.x; sv.y += p.y; sv.z += p.z; sv.w += p.w;
        *(float4*)(g_Sv + idx) = sv;
        float4 sx = *(float4*)(g_Sx + idx);
        sx.x += wq * p.x; sx.y += wq * p.y; sx.z += wq * p.z; sx.w += wq * p.w;
        *(float4*)(g_Sx + idx) = sx;
    }
}

// ===========================================================================
// kFinal: dual GEMM (Sx, Sv) @ W, fused output:
//   x = x0 + 8dt*v0 + 64*dt*hdt*F - dt*hdt*(Sx@W)
//   v = v0 + 16*hdt*F - hdt*(Sv@W)
// Tile 128x64, K=256, grid (16,32), 256 thr.
// ===========================================================================
constexpr int F_LDA = 40, F_LDB = 72, F_LDG = 68;
constexpr int F_STAGE = 2 * 128 * F_LDA + 32 * F_LDB;   // 12544
constexpr int F_SMEM_F = (2 * F_STAGE > 2 * 128 * F_LDG) ? 2 * F_STAGE : 2 * 128 * F_LDG;
constexpr int F_SMEM   = F_SMEM_F * 4;                  // 100352 B

__global__ void __launch_bounds__(256, 1)
kFinal(const float* __restrict__ W, const float* __restrict__ x0,
       const float* __restrict__ v0, const float* __restrict__ Fin,
       float* __restrict__ Xw, float* __restrict__ Vw)
{
    extern __shared__ float smem[];
    const int bn = blockIdx.x, bm = blockIdx.y;
    const int tid = threadIdx.x, warp = tid >> 5;
    const int wRow = (warp & 3) * 32, wCol = (warp >> 2) * 32;

    AccF acc[2][2][2];
    #pragma unroll
    for (int o = 0; o < 2; o++)
        #pragma unroll
        for (int i = 0; i < 2; i++)
            #pragma unroll
            for (int j = 0; j < 2; j++) wmma::fill_fragment(acc[o][i][j], 0.0f);

    const float* Ag[2] = { g_Sx + (size_t)bm * 128 * Rr, g_Sv + (size_t)bm * 128 * Rr };
    const float* Bg = W + bn * 64;

    auto load_stage = [&](int kt, int s) {
        float* st = smem + s * F_STAGE;
        const int k0 = kt * 32;
        #pragma unroll
        for (int o = 0; o < 2; o++) {
            float* sA = st + o * 128 * F_LDA;
            #pragma unroll
            for (int it = 0; it < 4; it++) {
                int t = tid + it * 256;
                int r = t >> 3, c4 = t & 7;
                cp_async16(&sA[r * F_LDA + c4 * 4], Ag[o] + (size_t)r * Rr + k0 + c4 * 4);
            }
        }
        float* sB = st + 2 * 128 * F_LDA;
        #pragma unroll
        for (int it = 0; it < 2; it++) {
            int t = tid + it * 256;
            int r = t >> 4, c4 = t & 15;
            cp_async16(&sB[r * F_LDB + c4 * 4], Bg + (size_t)(k0 + r) * Dd + c4 * 4);
        }
        cp_commit();
    };

    constexpr int KT = Rr / 32;   // 8
    load_stage(0, 0);
    for (int kt = 0; kt < KT; kt++) {
        if (kt + 1 < KT) { load_stage(kt + 1, (kt + 1) & 1); cp_wait<1>(); }
        else             { cp_wait<0>(); }
        __syncthreads();
        const float* st = smem + (kt & 1) * F_STAGE;
        const float* sB = st + 2 * 128 * F_LDA;
        #pragma unroll
        for (int kk = 0; kk < 32; kk += 8) {
            AF af[2][2]; BF bf[2];
            #pragma unroll
            for (int o = 0; o < 2; o++)
                #pragma unroll
                for (int i = 0; i < 2; i++)
                    wmma::load_matrix_sync(af[o][i],
                        st + o * 128 * F_LDA + (wRow + i * 16) * F_LDA + kk, F_LDA);
            #pragma unroll
            for (int j = 0; j < 2; j++)
                wmma::load_matrix_sync(bf[j], sB + kk * F_LDB + wCol + j * 16, F_LDB);
            #pragma unroll
            for (int o = 0; o < 2; o++)
                #pragma unroll
                for (int i = 0; i < 2; i++)
                    #pragma unroll
                    for (int j = 0; j < 2; j++)
                        wmma::mma_sync(acc[o][i][j], af[o][i], bf[j], acc[o][i][j]);
        }
        __syncthreads();
    }

    float* sGx = smem;
    float* sGv = smem + 128 * F_LDG;
    #pragma unroll
    for (int i = 0; i < 2; i++)
        #pragma unroll
        for (int j = 0; j < 2; j++) {
            wmma::store_matrix_sync(&sGx[(wRow + i * 16) * F_LDG + wCol + j * 16],
                                    acc[0][i][j], F_LDG, wmma::mem_row_major);
            wmma::store_matrix_sync(&sGv[(wRow + i * 16) * F_LDG + wCol + j * 16],
                                    acc[1][i][j], F_LDG, wmma::mem_row_major);
        }
    __syncthreads();

    const float c_xv = 0.08f;        // 8*dt
    const float c_xf = 0.0032f;      // 64*dt*hdt
    const float c_xg = 5e-5f;        // dt*hdt
    const float c_vf = 0.08f;        // 16*hdt
    const float c_vg = 0.005f;       // hdt
    #pragma unroll
    for (int it = 0; it < 8; it++) {
        int u = tid + it * 256;
        int r = u >> 4, c4 = u & 15;
        float4 gx = *(float4*)&sGx[r * F_LDG + c4 * 4];
        float4 gv = *(float4*)&sGv[r * F_LDG + c4 * 4];
        size_t idx = (size_t)(bm * 128 + r) * Dd + bn * 64 + c4 * 4;
        float4 x = *(const float4*)(x0 + idx);
        float4 v = *(const float4*)(v0 + idx);
        float4 f = *(const float4*)(Fin + idx);
        float4 xo, vo;
        xo.x = x.x + c_xv * v.x + c_xf * f.x - c_xg * gx.x;
        xo.y = x.y + c_xv * v.y + c_xf * f.y - c_xg * gx.y;
        xo.z = x.z + c_xv * v.z + c_xf * f.z - c_xg * gx.z;
        xo.w = x.w + c_xv * v.w + c_xf * f.w - c_xg * gx.w;
        vo.x = v.x + c_vf * f.x - c_vg * gv.x;
        vo.y = v.y + c_vf * f.y - c_vg * gv.y;
        vo.z = v.z + c_vf * f.z - c_vg * gv.z;
        vo.w = v.w + c_vf * f.w - c_vg * gv.w;
        *(float4*)(Xw + idx) = xo;
        *(float4*)(Vw + idx) = vo;
    }
}

// ===========================================================================
extern "C" void kernel_launch(void* const* d_in, const int* in_sizes, int n_in,
                              void* d_out, int out_size)
{
    const float* x0 = (const float*)d_in[0];
    const float* v0 = (const float*)d_in[1];
    const float* F  = (const float*)d_in[2];
    const float* U  = (const float*)d_in[3];
    const float* W  = (const float*)d_in[4];

    float* Xw = (float*)d_out;
    float* Vw = Xw + (size_t)Bsz * Dd;

    cudaFuncSetAttribute(kInit, cudaFuncAttributeMaxDynamicSharedMemorySize, I_SMEM);
    cudaFuncSetAttribute(kWU,   cudaFuncAttributeMaxDynamicSharedMemorySize, W_SMEM);
    cudaFuncSetAttribute(kStep<true>,  cudaFuncAttributeMaxDynamicSharedMemorySize, S_SMEM);
    cudaFuncSetAttribute(kStep<false>, cudaFuncAttributeMaxDynamicSharedMemorySize, S_SMEM);
    cudaFuncSetAttribute(kFinal, cudaFuncAttributeMaxDynamicSharedMemorySize, F_SMEM);

    dim3 blk(256);

    kWU<<<dim3(2, 2, 8), blk, W_SMEM>>>(W, U);
    kRed<<<Rr * Rr / 256, 256>>>();
    kInit<<<dim3(4, 32), blk, I_SMEM>>>(x0, v0, F, U);

    // weight of produced P_{t+1}: u=t+1; u odd -> 7-(u-1)/2, u even -> 8-u/2
    const float wtab[15] = {7,7,6,6,5,5,4,4,3,3,2,2,1,1,0};
    for (int t = 0; t < 15; t++) {
        if ((t & 1) == 0) kStep<true ><<<dim3(4, 32), blk, S_SMEM>>>(wtab[t]);
        else              kStep<false><<<dim3(4, 32), blk, S_SMEM>>>(wtab[t]);
    }

    kFinal<<<dim3(16, 32), blk, F_SMEM>>>(W, x0, v0, F, Xw, Vw);
}